// round 2
// baseline (speedup 1.0000x reference)
#include <cuda_runtime.h>
#include <cuda_bf16.h>

// Problem shape (fixed by reference):
//   inputs:         [B=32, H=56, W=56, C=256] fp32
//   routing_inputs: [B=32, ROUTES=4]          fp32
//   out:            [B, H, W, RW=64]          fp32
// out[b,h,w,j] = inputs[b,h,w, argmax(routing[b])*64 + j]
// -> per-pixel contiguous 256B gather. Pure HBM-bound copy (~51.4 MB traffic).

namespace {
constexpr int B      = 32;
constexpr int HW     = 56 * 56;     // 3136
constexpr int C      = 256;
constexpr int ROUTES = 4;
constexpr int RW     = C / ROUTES;  // 64
constexpr int V      = RW / 4;      // 16 float4 per output pixel
constexpr int CV     = C / 4;       // 64 float4 per input pixel
constexpr int THREADS = 256;
constexpr long long TOTAL_V4 = (long long)B * HW * V;        // 1,605,632
constexpr int BLOCKS = (int)(TOTAL_V4 / THREADS);            // 6272
constexpr int BLOCKS_PER_BATCH = BLOCKS / B;                 // 196 (exact)
}

__global__ __launch_bounds__(THREADS)
void routing_gather_kernel(const float4* __restrict__ in4,
                           const float*  __restrict__ routing,
                           float4* __restrict__ out4)
{
    int i = blockIdx.x * THREADS + threadIdx.x;   // global float4 index
    int j = i & (V - 1);                          // float4-within-pixel, V=16
    int t = i >> 4;                               // b*HW + pix

    // Batch index from block id: each batch spans exactly 196 blocks.
    int b = blockIdx.x / BLOCKS_PER_BATCH;        // const-divisor -> mulhi

    // Per-thread argmax over 4 routing logits. Uniform address across the
    // block -> L1 broadcast. Strict '>' matches argmax first-max tie rule.
    const float* r = routing + b * ROUTES;
    float best = r[0];
    int route = 0;
#pragma unroll
    for (int k = 1; k < ROUTES; ++k) {
        float v = r[k];
        if (v > best) { best = v; route = k; }
    }

    // Input pixel base: t * CV ; select contiguous block route*V, lane j.
    out4[i] = __ldg(&in4[(long long)t * CV + route * V + j]);
}

extern "C" void kernel_launch(void* const* d_in, const int* in_sizes, int n_in,
                              void* d_out, int out_size)
{
    const float4* in4     = (const float4*)d_in[0];
    const float*  routing = (const float*)d_in[1];
    float4*       out4    = (float4*)d_out;

    routing_gather_kernel<<<BLOCKS, THREADS>>>(in4, routing, out4);
}

// round 3
// speedup vs baseline: 1.0685x; 1.0685x over previous
#include <cuda_runtime.h>
#include <cuda_bf16.h>

// inputs:  [B=32, 56, 56, C=256] fp32 ; routing: [32, 4] fp32
// out[b,h,w,j] = inputs[b,h,w, argmax(routing[b])*64 + j]  -> [32,56,56,64]
// Per-pixel contiguous 256B gather. Input is L2-resident (102MB < 126MB L2),
// so DRAM sees only the 25.7MB of stores; kernel is latency-bound -> raise MLP.

namespace {
constexpr int B       = 32;
constexpr int HW      = 56 * 56;      // 3136
constexpr int ROUTES  = 4;
constexpr int V       = 16;           // float4 per output pixel (64 floats)
constexpr int CV      = 64;           // float4 per input pixel (256 floats)
constexpr int THREADS = 256;
constexpr int PER_TH  = 4;            // float4 per thread (MLP=4)
constexpr int PER_BLK = THREADS * PER_TH;                 // 1024
constexpr long long TOTAL_V4 = (long long)B * HW * V;     // 1,605,632
constexpr int BLOCKS  = (int)(TOTAL_V4 / PER_BLK);        // 1568 (exact)
constexpr int BLOCKS_PER_BATCH = BLOCKS / B;              // 49   (exact)
}

__global__ __launch_bounds__(THREADS)
void routing_gather_kernel(const float4* __restrict__ in4,
                           const float*  __restrict__ routing,
                           float4* __restrict__ out4)
{
    // Block covers PER_BLK consecutive output float4s, all in one batch b.
    const int b = blockIdx.x / BLOCKS_PER_BATCH;

    // argmax over 4 logits; uniform address across block -> L1/L2 broadcast.
    const float* r = routing + b * ROUTES;
    float best = r[0];
    int route = 0;
#pragma unroll
    for (int k = 1; k < ROUTES; ++k) {
        float v = r[k];
        if (v > best) { best = v; route = k; }
    }
    const int rbase = route * V;

    const int base = blockIdx.x * PER_BLK
                   + (threadIdx.x >> 5) * (32 * PER_TH)   // warp's 128-f4 chunk
                   + (threadIdx.x & 31);                  // lane

    // 4 independent coalesced loads (front-batched by ptxas), then 4 stores.
    float4 v[PER_TH];
#pragma unroll
    for (int k = 0; k < PER_TH; ++k) {
        int idx = base + k * 32;          // global output float4 index
        int t   = idx >> 4;               // pixel index (b*HW + pix)
        int j   = idx & (V - 1);          // float4 within pixel
        v[k] = __ldg(&in4[(long long)t * CV + rbase + j]);
    }
#pragma unroll
    for (int k = 0; k < PER_TH; ++k) {
        out4[base + k * 32] = v[k];
    }
}

extern "C" void kernel_launch(void* const* d_in, const int* in_sizes, int n_in,
                              void* d_out, int out_size)
{
    const float4* in4     = (const float4*)d_in[0];
    const float*  routing = (const float*)d_in[1];
    float4*       out4    = (float4*)d_out;

    routing_gather_kernel<<<BLOCKS, THREADS>>>(in4, routing, out4);
}